// round 14
// baseline (speedup 1.0000x reference)
#include <cuda_runtime.h>
#include <math.h>
#include <cstdint>
#include <mma.h>
using namespace nvcuda;

// ---------------- problem constants ----------------
#define B_    2
#define S_    2048
#define DIM_  2048
#define H_    16
#define NOPE_ 128
#define ROPE_ 64
#define VDIM_ 128
#define QR_   1024
#define KVR_  512
#define MTOK  (B_*S_)          // 4096
#define QKD   (NOPE_+ROPE_)    // 192
#define BH_   (B_*H_)          // 32

// ---------------- scratch ----------------
__device__ float g_qc   [(long long)MTOK*QR_];
__device__ float g_qnope[(long long)MTOK*H_*NOPE_];
__device__ float g_qpe  [(long long)MTOK*H_*ROPE_];
__device__ float g_kvc  [(long long)MTOK*KVR_];
__device__ float g_kvup [(long long)MTOK*H_*(NOPE_+VDIM_)];
__device__ float g_krope[(long long)MTOK*ROPE_];
__device__ float g_attn [(long long)MTOK*H_*VDIM_];
// tf32-rounded operand copies
__device__ float g_xr [(long long)MTOK*DIM_];
__device__ float g_w1 [(long long)QR_*DIM_];
__device__ float g_w2 [(long long)H_*NOPE_*QR_];
__device__ float g_w3 [(long long)H_*ROPE_*QR_];
__device__ float g_w4 [(long long)KVR_*DIM_];
__device__ float g_w5 [(long long)H_*(NOPE_+VDIM_)*KVR_];
__device__ float g_w6 [(long long)ROPE_*DIM_];
__device__ float g_w7 [(long long)DIM_*H_*VDIM_];

// ---------------- helpers ----------------
__device__ __forceinline__ unsigned f2tf(float f) {
    unsigned r; asm("cvt.rna.tf32.f32 %0, %1;" : "=r"(r) : "f"(f)); return r;
}
__device__ __forceinline__ float rtf(float x) { return __uint_as_float(f2tf(x)); }

__device__ __forceinline__ void mma_tf32(float c[4], const unsigned a[4], const unsigned b[2]) {
    asm volatile(
        "mma.sync.aligned.m16n8k8.row.col.f32.tf32.tf32.f32 "
        "{%0,%1,%2,%3},{%4,%5,%6,%7},{%8,%9},{%0,%1,%2,%3};"
        : "+f"(c[0]), "+f"(c[1]), "+f"(c[2]), "+f"(c[3])
        : "r"(a[0]), "r"(a[1]), "r"(a[2]), "r"(a[3]), "r"(b[0]), "r"(b[1]));
}

__device__ __forceinline__ void cpasync16(void* s, const void* g) {
    unsigned saddr = (unsigned)__cvta_generic_to_shared(s);
    asm volatile("cp.async.ca.shared.global [%0], [%1], 16;" :: "r"(saddr), "l"(g));
}

// =====================================================================
// NT TF32 GEMM, cp.async 3-stage (.ca), tile 128 x NT x 32, 8 warps,
// single __syncthreads per k-tile.
// =====================================================================
template<int NT>
__device__ __forceinline__ void gemm_issue(const float* A, const float* B,
                                           float* SA, float* SB,
                                           int bm, int bn, int K, int kt, int st, int tid)
{
    const int k0 = kt << 5;
    #pragma unroll
    for (int l = 0; l < 4; l++) {
        int idx = tid + (l << 8);
        int r = idx >> 3, c4 = (idx & 7) << 2;
        cpasync16(&SA[st * 4608 + r * 36 + c4], &A[(long long)(bm * 128 + r) * K + k0 + c4]);
    }
    #pragma unroll
    for (int l = 0; l < NT / 32; l++) {
        int idx = tid + (l << 8);
        int r = idx >> 3, c4 = (idx & 7) << 2;
        cpasync16(&SB[st * (NT * 36) + r * 36 + c4], &B[(long long)(bn * NT + r) * K + k0 + c4]);
    }
    asm volatile("cp.async.commit_group;");
}

template<int NT, bool RND>
__device__ __forceinline__ void gemm_core(const float* A, const float* Bm, float* C,
                                          int bm, int bn, int N, int K, float* smg)
{
    float* SA = smg;                  // [3][128*36]
    float* SB = smg + 3 * 4608;       // [3][NT*36]

    constexpr int WN = NT / 32;
    constexpr int WMC = 8 / WN;
    constexpr int FM = (128 / WMC) / 16;

    const int tid = threadIdx.x;
    const int w = tid >> 5;
    const int wm = w / WN, wn = w % WN;

    wmma::fragment<wmma::accumulator, 16, 16, 8, float> cf[FM][2];
    #pragma unroll
    for (int i = 0; i < FM; i++)
        #pragma unroll
        for (int j = 0; j < 2; j++)
            wmma::fill_fragment(cf[i][j], 0.0f);

    const int nk = K >> 5;
    gemm_issue<NT>(A, Bm, SA, SB, bm, bn, K, 0, 0, tid);
    gemm_issue<NT>(A, Bm, SA, SB, bm, bn, K, 1, 1, tid);

    for (int kt = 0; kt < nk; kt++) {
        const int st = kt % 3;
        if (kt + 1 < nk) asm volatile("cp.async.wait_group 1;");
        else             asm volatile("cp.async.wait_group 0;");
        __syncthreads();
        if (kt + 2 < nk)
            gemm_issue<NT>(A, Bm, SA, SB, bm, bn, K, kt + 2, (kt + 2) % 3, tid);

        float* As = SA + st * 4608;
        float* Bs = SB + st * (NT * 36);
        #pragma unroll
        for (int kk = 0; kk < 4; kk++) {
            wmma::fragment<wmma::matrix_a, 16, 16, 8, wmma::precision::tf32, wmma::row_major> af[FM];
            #pragma unroll
            for (int i = 0; i < FM; i++)
                wmma::load_matrix_sync(af[i], &As[(wm * (FM * 16) + i * 16) * 36 + kk * 8], 36);
            wmma::fragment<wmma::matrix_b, 16, 16, 8, wmma::precision::tf32, wmma::col_major> bf[2];
            #pragma unroll
            for (int j = 0; j < 2; j++)
                wmma::load_matrix_sync(bf[j], &Bs[(wn * 32 + j * 16) * 36 + kk * 8], 36);
            #pragma unroll
            for (int i = 0; i < FM; i++)
                #pragma unroll
                for (int j = 0; j < 2; j++)
                    wmma::mma_sync(cf[i][j], af[i], bf[j], cf[i][j]);
        }
    }

    #pragma unroll
    for (int i = 0; i < FM; i++)
        #pragma unroll
        for (int j = 0; j < 2; j++) {
            if (RND) {
                #pragma unroll
                for (int t = 0; t < cf[i][j].num_elements; t++)
                    cf[i][j].x[t] = rtf(cf[i][j].x[t]);
            }
            wmma::store_matrix_sync(
                &C[(long long)(bm * 128 + wm * (FM * 16) + i * 16) * N + bn * NT + wn * 32 + j * 16],
                cf[i][j], (unsigned)N, wmma::mem_row_major);
        }
}

template<int NT, bool RND>
__global__ __launch_bounds__(256, 2)
void gemm_nt(const float* __restrict__ A, const float* __restrict__ Bm,
             float* __restrict__ C, int N, int K)
{
    extern __shared__ float smg[];
    gemm_core<NT, RND>(A, Bm, C, blockIdx.y, blockIdx.x, N, K, smg);
}

// three GEMMs sharing A: B1(128-tiles), B2(128-tiles), B3(one 64-tile)
__global__ __launch_bounds__(256, 2)
void gemm_nt_tri(const float* __restrict__ A,
                 const float* __restrict__ B1, float* __restrict__ C1, int N1, int n1,
                 const float* __restrict__ B2, float* __restrict__ C2, int N2, int n2,
                 const float* __restrict__ B3, float* __restrict__ C3, int N3,
                 int K)
{
    extern __shared__ float smg[];
    int bx = blockIdx.x;
    if (bx < n1)           gemm_core<128, false>(A, B1, C1, blockIdx.y, bx, N1, K, smg);
    else if (bx < n1 + n2) gemm_core<128, false>(A, B2, C2, blockIdx.y, bx - n1, N2, K, smg);
    else                   gemm_core<64,  false>(A, B3, C3, blockIdx.y, 0, N3, K, smg);
}

// merged mid-pipeline launch: q_nope || q_pe || kv_up (rounded store)
__global__ __launch_bounds__(256, 2)
void gemm_mid(const float* __restrict__ qc,
              const float* __restrict__ w2, float* __restrict__ qn,
              const float* __restrict__ w3, float* __restrict__ qp,
              const float* __restrict__ kvc,
              const float* __restrict__ w5, float* __restrict__ kvu)
{
    extern __shared__ float smg[];
    int bx = blockIdx.x;
    if (bx < 16)      gemm_core<128, false>(qc,  w2, qn,  blockIdx.y, bx,      H_*NOPE_,          QR_,  smg);
    else if (bx < 24) gemm_core<128, false>(qc,  w3, qp,  blockIdx.y, bx - 16, H_*ROPE_,          QR_,  smg);
    else              gemm_core<128, true >(kvc, w5, kvu, blockIdx.y, bx - 24, H_*(NOPE_+VDIM_),  KVR_, smg);
}

// ---------------- single merged tf32 rounding pass ----------------
__device__ __forceinline__ void round_seg(const float* in, float* outp, long long n4,
                                          long long start, long long stride)
{
    for (long long i = start; i < n4; i += stride) {
        float4 v = ((const float4*)in)[i];
        ((float4*)outp)[i] = make_float4(rtf(v.x), rtf(v.y), rtf(v.z), rtf(v.w));
    }
}

__global__ void round_all_k(const float* x,  float* xr,
                            const float* a1, float* o1,
                            const float* a2, float* o2,
                            const float* a3, float* o3,
                            const float* a4, float* o4,
                            const float* a5, float* o5,
                            const float* a6, float* o6,
                            const float* a7, float* o7)
{
    long long start = (long long)blockIdx.x * 256 + threadIdx.x;
    long long stride = (long long)gridDim.x * 256;
    round_seg(x,  xr, (long long)MTOK * DIM_ / 4,               start, stride);
    round_seg(a1, o1, (long long)QR_ * DIM_ / 4,                start, stride);
    round_seg(a2, o2, (long long)H_ * NOPE_ * QR_ / 4,          start, stride);
    round_seg(a3, o3, (long long)H_ * ROPE_ * QR_ / 4,          start, stride);
    round_seg(a4, o4, (long long)KVR_ * DIM_ / 4,               start, stride);
    round_seg(a5, o5, (long long)H_ * (NOPE_+VDIM_) * KVR_ / 4, start, stride);
    round_seg(a6, o6, (long long)ROPE_ * DIM_ / 4,              start, stride);
    round_seg(a7, o7, (long long)DIM_ * H_ * VDIM_ / 4,         start, stride);
}

// =====================================================================
// Fused flash attention v6 (R11 exact): split-K PV with register P.
// =====================================================================
__global__ __launch_bounds__(256, 1)
void flash_attn(const float* __restrict__ qn, const float* __restrict__ qp,
                const float* __restrict__ kvu, const float* __restrict__ kr,
                float* __restrict__ outp)
{
    extern __shared__ float sm[];
    float* QS   = sm;          // [128][196]   (25088 floats)
    float* KS   = sm + 25088;  // [64][196]    (12544 floats)
    float* VS   = sm + 37632;  // [64][132]    (8448 floats)
    float* PMAX = sm + 46080;  // [2][128]
    float* LX   = sm + 46336;  // [128]
    float* OX   = sm + 25088;  // epilogue only: overlays KS+VS, [128][132]

    const int qt = (int)gridDim.x - 1 - (int)blockIdx.x;
    const int bh = blockIdx.y;
    const int b = bh >> 4, h = bh & 15;
    const int ib = qt * 128;
    const long long bs0 = (long long)b * S_;

    const int tid = threadIdx.x;
    const int w = tid >> 5, lane = tid & 31;
    const int wm = w & 3, wn = w >> 2;
    const int g = lane >> 2, t = lane & 3;
    const float scale = 0.07216878364870323f;

    const int ntiles = (ib + 128) / 64;

    // ---- preload K(0), V(0) as two groups ----
    {
        long long rowb = bs0;
        for (int i = tid; i < 64 * 48; i += 256) {
            int r = i / 48, c4 = i % 48;
            long long row = rowb + r;
            const float* src = (c4 < 32)
                ? &kvu[row * 4096 + h * 256 + c4 * 4]
                : &kr[row * 64 + (c4 - 32) * 4];
            cpasync16(&KS[r * 196 + c4 * 4], src);
        }
        asm volatile("cp.async.commit_group;");
        for (int i = tid; i < 64 * 32; i += 256) {
            int r = i / 32, c4 = i % 32;
            cpasync16(&VS[r * 132 + c4 * 4], &kvu[(rowb + r) * 4096 + h * 256 + 128 + c4 * 4]);
        }
        asm volatile("cp.async.commit_group;");
    }

    // ---- load Q tile (scaled + rounded) ----
    for (int i = tid; i < 128 * 48; i += 256) {
        int r = i / 48, c4 = (i % 48) * 4;
        long long row = bs0 + ib + r;
        float4 v;
        if (c4 < 128) v = *(const float4*)&qn[row * 2048 + h * 128 + c4];
        else          v = *(const float4*)&qp[row * 1024 + h * 64 + (c4 - 128)];
        float* d = &QS[r * 196 + c4];
        d[0] = rtf(v.x * scale); d[1] = rtf(v.y * scale);
        d[2] = rtf(v.z * scale); d[3] = rtf(v.w * scale);
    }

    float m[2][2] = {{-1e30f, -1e30f}, {-1e30f, -1e30f}};
    float l[2][2] = {{0.f, 0.f}, {0.f, 0.f}};
    float oacc[2][16][4] = {};

    const int srcl = (lane & 28) | (t >> 1);
    const int srch = srcl + 2;
    const bool todd = (t & 1);

    for (int kt = 0; kt < ntiles; kt++) {
        const int jb = kt * 64;

        asm volatile("cp.async.wait_group 1;");   // K(kt) ready
        __syncthreads();

        // ---- S = Q K^T ----
        float sacc[2][4][4] = {};
        #pragma unroll
        for (int k = 0; k < 24; k++) {
            unsigned a[2][4];
            #pragma unroll
            for (int mf = 0; mf < 2; mf++) {
                int r0 = wm * 32 + mf * 16 + g;
                a[mf][0] = __float_as_uint(QS[r0 * 196 + k * 8 + t]);
                a[mf][1] = __float_as_uint(QS[(r0 + 8) * 196 + k * 8 + t]);
                a[mf][2] = __float_as_uint(QS[r0 * 196 + k * 8 + t + 4]);
                a[mf][3] = __float_as_uint(QS[(r0 + 8) * 196 + k * 8 + t + 4]);
            }
            #pragma unroll
            for (int nf = 0; nf < 4; nf++) {
                unsigned bb[2];
                int n0 = wn * 32 + nf * 8 + g;
                bb[0] = __float_as_uint(KS[n0 * 196 + k * 8 + t]);
                bb[1] = __float_as_uint(KS[n0 * 196 + k * 8 + t + 4]);
                mma_tf32(sacc[0][nf], a[0], bb);
                mma_tf32(sacc[1][nf], a[1], bb);
            }
        }

        // ---- causal mask ----
        if (jb + 63 > ib) {
            #pragma unroll
            for (int mf = 0; mf < 2; mf++)
                #pragma unroll
                for (int nf = 0; nf < 4; nf++)
                    #pragma unroll
                    for (int e = 0; e < 4; e++) {
                        int row = ib + wm * 32 + mf * 16 + g + ((e >> 1) << 3);
                        int col = jb + wn * 32 + nf * 8 + 2 * t + (e & 1);
                        if (col > row) sacc[mf][nf][e] = -1e30f;
                    }
        }

        // ---- per-row max over own key half; publish ----
        float rmax[2][2];
        #pragma unroll
        for (int mf = 0; mf < 2; mf++)
            #pragma unroll
            for (int hf = 0; hf < 2; hf++) {
                float v = -1e30f;
                #pragma unroll
                for (int nf = 0; nf < 4; nf++)
                    v = fmaxf(v, fmaxf(sacc[mf][nf][2 * hf], sacc[mf][nf][2 * hf + 1]));
                v = fmaxf(v, __shfl_xor_sync(0xFFFFFFFF, v, 1));
                v = fmaxf(v, __shfl_xor_sync(0xFFFFFFFF, v, 2));
                rmax[mf][hf] = v;
            }
        if (t == 0) {
            #pragma unroll
            for (int mf = 0; mf < 2; mf++)
                #pragma unroll
                for (int hf = 0; hf < 2; hf++)
                    PMAX[wn * 128 + wm * 32 + mf * 16 + hf * 8 + g] = rmax[mf][hf];
        }
        __syncthreads();   // KS reads done + PMAX visible

        // ---- issue K(kt+1) ----
        if (kt + 1 < ntiles) {
            long long rowb = bs0 + jb + 64;
            for (int i = tid; i < 64 * 48; i += 256) {
                int r = i / 48, c4 = i % 48;
                long long row = rowb + r;
                const float* src = (c4 < 32)
                    ? &kvu[row * 4096 + h * 256 + c4 * 4]
                    : &kr[row * 64 + (c4 - 32) * 4];
                cpasync16(&KS[r * 196 + c4 * 4], src);
            }
            asm volatile("cp.async.commit_group;");
        }

        // ---- global m update ----
        float c[2][2];
        #pragma unroll
        for (int mf = 0; mf < 2; mf++)
            #pragma unroll
            for (int hf = 0; hf < 2; hf++) {
                float other = PMAX[(wn ^ 1) * 128 + wm * 32 + mf * 16 + hf * 8 + g];
                float mn = fmaxf(m[mf][hf], fmaxf(rmax[mf][hf], other));
                c[mf][hf] = __expf(m[mf][hf] - mn);
                m[mf][hf] = mn;
            }

        // ---- P = exp(S - m) in registers; shuffle into mma-A layout ----
        unsigned af[2][4][4];
        float rsum[2][2] = {};
        #pragma unroll
        for (int mf = 0; mf < 2; mf++) {
            #pragma unroll
            for (int nf = 0; nf < 4; nf++) {
                float p0 = rtf(__expf(sacc[mf][nf][0] - m[mf][0]));
                float p1 = rtf(__expf(sacc[mf][nf][1] - m[mf][0]));
                float p2 = rtf(__expf(sacc[mf][nf][2] - m[mf][1]));
                float p3 = rtf(__expf(sacc[mf][nf][3] - m[mf][1]));
                rsum[mf][0] += p0 + p1;
                rsum[mf][1] += p2 + p3;
                float y0, y1;
                y0 = __shfl_sync(0xFFFFFFFF, p0, srcl);
                y1 = __shfl_sync(0xFFFFFFFF, p1, srcl);
                af[mf][nf][0] = __float_as_uint(todd ? y1 : y0);
                y0 = __shfl_sync(0xFFFFFFFF, p2, srcl);
                y1 = __shfl_sync(0xFFFFFFFF, p3, srcl);
                af[mf][nf][1] = __float_as_uint(todd ? y1 : y0);
                y0 = __shfl_sync(0xFFFFFFFF, p0, srch);
                y1 = __shfl_sync(0xFFFFFFFF, p1, srch);
                af[mf][nf][2] = __float_as_uint(todd ? y1 : y0);
                y0 = __shfl_sync(0xFFFFFFFF, p2, srch);
                y1 = __shfl_sync(0xFFFFFFFF, p3, srch);
                af[mf][nf][3] = __float_as_uint(todd ? y1 : y0);
            }
        }
        #pragma unroll
        for (int mf = 0; mf < 2; mf++)
            #pragma unroll
            for (int hf = 0; hf < 2; hf++) {
                float v = rsum[mf][hf];
                v += __shfl_xor_sync(0xFFFFFFFF, v, 1);
                v += __shfl_xor_sync(0xFFFFFFFF, v, 2);
                l[mf][hf] = l[mf][hf] * c[mf][hf] + v;
            }

        // ---- rescale partial O ----
        #pragma unroll
        for (int mf = 0; mf < 2; mf++)
            #pragma unroll
            for (int nf = 0; nf < 16; nf++) {
                oacc[mf][nf][0] *= c[mf][0]; oacc[mf][nf][1] *= c[mf][0];
                oacc[mf][nf][2] *= c[mf][1]; oacc[mf][nf][3] *= c[mf][1];
            }

        // ---- V(kt) ready ----
        if (kt + 1 < ntiles) asm volatile("cp.async.wait_group 1;");
        else                 asm volatile("cp.async.wait_group 0;");
        __syncthreads();

        // ---- O_partial += P(own keys) V(own keys, :) ----
        #pragma unroll
        for (int kk = 0; kk < 4; kk++) {
            const int krow = wn * 32 + kk * 8;
            #pragma unroll
            for (int nf = 0; nf < 16; nf++) {
                unsigned bb[2];
                int n0 = nf * 8 + g;
                bb[0] = __float_as_uint(VS[(krow + t) * 132 + n0]);
                bb[1] = __float_as_uint(VS[(krow + t + 4) * 132 + n0]);
                mma_tf32(oacc[0][nf], af[0][kk], bb);
                mma_tf32(oacc[1][nf], af[1][kk], bb);
            }
        }
        __syncthreads();   // VS reads done

        // ---- issue V(kt+1) ----
        if (kt + 1 < ntiles) {
            long long rowb = bs0 + jb + 64;
            for (int i = tid; i < 64 * 32; i += 256) {
                int r = i / 32, c4 = i % 32;
                cpasync16(&VS[r * 132 + c4 * 4],
                          &kvu[(rowb + r) * 4096 + h * 256 + 128 + c4 * 4]);
            }
            asm volatile("cp.async.commit_group;");
        }
    }

    // ---- epilogue: reduce wn partials (O, l) and write out ----
    __syncthreads();
    if (wn == 1) {
        #pragma unroll
        for (int mf = 0; mf < 2; mf++) {
            int r0 = wm * 32 + mf * 16 + g;
            #pragma unroll
            for (int nf = 0; nf < 16; nf++) {
                int c2 = nf * 8 + 2 * t;
                *(float2*)&OX[r0 * 132 + c2]       = make_float2(oacc[mf][nf][0], oacc[mf][nf][1]);
                *(float2*)&OX[(r0 + 8) * 132 + c2] = make_float2(oacc[mf][nf][2], oacc[mf][nf][3]);
            }
            if (t == 0) { LX[r0] = l[mf][0]; LX[r0 + 8] = l[mf][1]; }
        }
    }
    __syncthreads();
    if (wn == 0) {
        #pragma unroll
        for (int mf = 0; mf < 2; mf++) {
            int r0 = wm * 32 + mf * 16 + g;
            float inv0 = 1.f / (l[mf][0] + LX[r0]);
            float inv1 = 1.f / (l[mf][1] + LX[r0 + 8]);
            long long o0 = (bs0 + ib + r0) * 2048 + h * 128;
            long long o1 = o0 + 8 * 2048;
            #pragma unroll
            for (int nf = 0; nf < 16; nf++) {
                int c2 = nf * 8 + 2 * t;
                float2 x0 = *(float2*)&OX[r0 * 132 + c2];
                float2 x1 = *(float2*)&OX[(r0 + 8) * 132 + c2];
                *(float2*)&outp[o0 + c2] =
                    make_float2(rtf((oacc[mf][nf][0] + x0.x) * inv0),
                                rtf((oacc[mf][nf][1] + x0.y) * inv0));
                *(float2*)&outp[o1 + c2] =
                    make_float2(rtf((oacc[mf][nf][2] + x1.x) * inv1),
                                rtf((oacc[mf][nf][3] + x1.y) * inv1));
            }
        }
    }
}

// ---------------- merged RMSNorm (qc rows then kvc rows) ----------------
__global__ void rmsnorm_dual_k(float* __restrict__ xq, const float* __restrict__ wq,
                               float* __restrict__ xk, const float* __restrict__ wk)
{
    int bid = blockIdx.x;
    float* p;
    const float* wv;
    int N;
    if (bid < MTOK) { p = xq + (long long)bid * QR_;          wv = wq; N = QR_; }
    else            { p = xk + (long long)(bid - MTOK) * KVR_; wv = wk; N = KVR_; }
    int tid = threadIdx.x;
    float ss = 0.f;
    for (int i = tid; i < N; i += 256) { float v = p[i]; ss += v * v; }
    __shared__ float red[256];
    red[tid] = ss; __syncthreads();
    for (int s = 128; s > 0; s >>= 1) { if (tid < s) red[tid] += red[tid + s]; __syncthreads(); }
    float scale = rsqrtf(red[0] / N + 1e-6f);
    for (int i = tid; i < N; i += 256) p[i] = rtf(p[i] * scale * wv[i]);
}

// ---------------- RoPE (write tf32-rounded) ----------------
__global__ void rope_q_k(float* __restrict__ qpe)
{
    int row = blockIdx.x;
    int s = row % S_;
    float* base = qpe + (long long)row * (H_ * ROPE_);
    for (int idx = threadIdx.x; idx < H_ * (ROPE_ / 2); idx += 256) {
        int h = idx >> 5, i = idx & 31;
        float fr = (float)s * powf(10000.f, -(2.f * i) / (float)ROPE_);
        float sn, c; sincosf(fr, &sn, &c);
        float* q = base + h * ROPE_;
        float x1 = q[2 * i], x2 = q[2 * i + 1];
        q[2 * i]     = rtf(x1 * c - x2 * sn);
        q[2 * i + 1] = rtf(x1 * sn + x2 * c);
    }
}

__global__ void rope_kr_k(float* __restrict__ kr)
{
    int row = blockIdx.x;
    int s = row % S_;
    float* q = kr + (long long)row * ROPE_;
    int i = threadIdx.x;
    float fr = (float)s * powf(10000.f, -(2.f * i) / (float)ROPE_);
    float sn, c; sincosf(fr, &sn, &c);
    float x1 = q[2 * i], x2 = q[2 * i + 1];
    q[2 * i]     = rtf(x1 * c - x2 * sn);
    q[2 * i + 1] = rtf(x1 * sn + x2 * c);
}

// ---------------- launch ----------------
extern "C" void kernel_launch(void* const* d_in, const int* in_sizes, int n_in,
                              void* d_out, int out_size)
{
    const float* x        = (const float*)d_in[0];
    const float* wq_down  = (const float*)d_in[1];
    const float* q_norm   = (const float*)d_in[2];
    const float* wq_up    = (const float*)d_in[3];
    const float* wq_rope  = (const float*)d_in[4];
    const float* wkv_down = (const float*)d_in[5];
    const float* kv_norm  = (const float*)d_in[6];
    const float* wkv_up   = (const float*)d_in[7];
    const float* wk_rope  = (const float*)d_in[8];
    const float* wo       = (const float*)d_in[9];
    float* out = (float*)d_out;

    float *qc, *qn, *qp, *kvc, *kvu, *kr, *attn;
    float *xr, *w1, *w2, *w3, *w4, *w5, *w6, *w7;
    cudaGetSymbolAddress((void**)&qc,   g_qc);
    cudaGetSymbolAddress((void**)&qn,   g_qnope);
    cudaGetSymbolAddress((void**)&qp,   g_qpe);
    cudaGetSymbolAddress((void**)&kvc,  g_kvc);
    cudaGetSymbolAddress((void**)&kvu,  g_kvup);
    cudaGetSymbolAddress((void**)&kr,   g_krope);
    cudaGetSymbolAddress((void**)&attn, g_attn);
    cudaGetSymbolAddress((void**)&xr,   g_xr);
    cudaGetSymbolAddress((void**)&w1,   g_w1);
    cudaGetSymbolAddress((void**)&w2,   g_w2);
    cudaGetSymbolAddress((void**)&w3,   g_w3);
    cudaGetSymbolAddress((void**)&w4,   g_w4);
    cudaGetSymbolAddress((void**)&w5,   g_w5);
    cudaGetSymbolAddress((void**)&w6,   g_w6);
    cudaGetSymbolAddress((void**)&w7,   g_w7);

    const int GS = 110592;     // gemm smem: 3 stages x (128+128)x36 floats
    const int FS = 186368;     // flash smem

    cudaFuncSetAttribute((const void*)gemm_nt<128,false>, cudaFuncAttributeMaxDynamicSharedMemorySize, GS);
    cudaFuncSetAttribute((const void*)gemm_nt_tri,        cudaFuncAttributeMaxDynamicSharedMemorySize, GS);
    cudaFuncSetAttribute((const void*)gemm_mid,           cudaFuncAttributeMaxDynamicSharedMemorySize, GS);
    cudaFuncSetAttribute((const void*)flash_attn,         cudaFuncAttributeMaxDynamicSharedMemorySize, FS);

    dim3 blk(256);

    // ---- single merged rounding pass ----
    round_all_k<<<1184, 256>>>(x, xr, wq_down, w1, wq_up, w2, wq_rope, w3,
                               wkv_down, w4, wkv_up, w5, wk_rope, w6, wo, w7);

    // fused: q_c (8 tiles) || kv_c (4 tiles) || k_rope (1x64 tile), A = xr
    gemm_nt_tri<<<dim3(13, MTOK/128), blk, GS>>>(
        xr, w1, qc, QR_, QR_/128, w4, kvc, KVR_, KVR_/128, w6, kr, ROPE_, DIM_);
    rope_kr_k<<<MTOK, 32>>>(kr);

    // merged rmsnorm (qc + kvc, one launch)
    rmsnorm_dual_k<<<2 * MTOK, 256>>>(qc, q_norm, kvc, kv_norm);

    // merged mid GEMMs: q_nope || q_pe || kv_up
    gemm_mid<<<dim3(56, MTOK/128), blk, GS>>>(qc, w2, qn, w3, qp, kvc, w5, kvu);

    rope_q_k<<<MTOK, 256>>>(qp);

    // fused attention -> attn (tf32-rounded)
    flash_attn<<<dim3(S_/128, BH_), 256, FS>>>(qn, qp, kvu, kr, attn);
    // out = attn @ wo^T
    gemm_nt<128,false><<<dim3(DIM_/128, MTOK/128), blk, GS>>>(attn, w7, out, DIM_, DIM_);
}

// round 15
// speedup vs baseline: 1.0619x; 1.0619x over previous
#include <cuda_runtime.h>
#include <math.h>
#include <cstdint>
#include <mma.h>
using namespace nvcuda;

// ---------------- problem constants ----------------
#define B_    2
#define S_    2048
#define DIM_  2048
#define H_    16
#define NOPE_ 128
#define ROPE_ 64
#define VDIM_ 128
#define QR_   1024
#define KVR_  512
#define MTOK  (B_*S_)          // 4096
#define QKD   (NOPE_+ROPE_)    // 192
#define BH_   (B_*H_)          // 32

// ---------------- scratch ----------------
__device__ float g_qc   [(long long)MTOK*QR_];
__device__ float g_qnope[(long long)MTOK*H_*NOPE_];
__device__ float g_qpe  [(long long)MTOK*H_*ROPE_];
__device__ float g_kvc  [(long long)MTOK*KVR_];
__device__ float g_kvup [(long long)MTOK*H_*(NOPE_+VDIM_)];
__device__ float g_krope[(long long)MTOK*ROPE_];
__device__ float g_attn [(long long)MTOK*H_*VDIM_];
// tf32-rounded operand copies
__device__ float g_xr [(long long)MTOK*DIM_];
__device__ float g_w1 [(long long)QR_*DIM_];
__device__ float g_w2 [(long long)H_*NOPE_*QR_];
__device__ float g_w3 [(long long)H_*ROPE_*QR_];
__device__ float g_w4 [(long long)KVR_*DIM_];
__device__ float g_w5 [(long long)H_*(NOPE_+VDIM_)*KVR_];
__device__ float g_w6 [(long long)ROPE_*DIM_];
__device__ float g_w7 [(long long)DIM_*H_*VDIM_];

// ---------------- helpers ----------------
__device__ __forceinline__ unsigned f2tf(float f) {
    unsigned r; asm("cvt.rna.tf32.f32 %0, %1;" : "=r"(r) : "f"(f)); return r;
}
__device__ __forceinline__ float rtf(float x) { return __uint_as_float(f2tf(x)); }

__device__ __forceinline__ void mma_tf32(float c[4], const unsigned a[4], const unsigned b[2]) {
    asm volatile(
        "mma.sync.aligned.m16n8k8.row.col.f32.tf32.tf32.f32 "
        "{%0,%1,%2,%3},{%4,%5,%6,%7},{%8,%9},{%0,%1,%2,%3};"
        : "+f"(c[0]), "+f"(c[1]), "+f"(c[2]), "+f"(c[3])
        : "r"(a[0]), "r"(a[1]), "r"(a[2]), "r"(a[3]), "r"(b[0]), "r"(b[1]));
}

__device__ __forceinline__ void cpasync16(void* s, const void* g) {
    unsigned saddr = (unsigned)__cvta_generic_to_shared(s);
    asm volatile("cp.async.ca.shared.global [%0], [%1], 16;" :: "r"(saddr), "l"(g));
}

// =====================================================================
// NT TF32 GEMM, cp.async 2-stage (R13 exact), tile 128 x NT x 32, 8 warps.
// =====================================================================
template<int NT>
__device__ __forceinline__ void gemm_issue(const float* A, const float* B,
                                           float* SA, float* SB,
                                           int bm, int bn, int K, int kt, int st, int tid)
{
    const int k0 = kt << 5;
    #pragma unroll
    for (int l = 0; l < 4; l++) {
        int idx = tid + (l << 8);
        int r = idx >> 3, c4 = (idx & 7) << 2;
        cpasync16(&SA[st * 4608 + r * 36 + c4], &A[(long long)(bm * 128 + r) * K + k0 + c4]);
    }
    #pragma unroll
    for (int l = 0; l < NT / 32; l++) {
        int idx = tid + (l << 8);
        int r = idx >> 3, c4 = (idx & 7) << 2;
        cpasync16(&SB[st * (NT * 36) + r * 36 + c4], &B[(long long)(bn * NT + r) * K + k0 + c4]);
    }
    asm volatile("cp.async.commit_group;");
}

template<int NT, bool RND>
__device__ __forceinline__ void gemm_core(const float* A, const float* Bm, float* C,
                                          int bm, int bn, int N, int K, float* smg)
{
    float* SA = smg;
    float* SB = smg + 2 * 4608;

    constexpr int WN = NT / 32;
    constexpr int WMC = 8 / WN;
    constexpr int FM = (128 / WMC) / 16;

    const int tid = threadIdx.x;
    const int w = tid >> 5;
    const int wm = w / WN, wn = w % WN;

    wmma::fragment<wmma::accumulator, 16, 16, 8, float> cf[FM][2];
    #pragma unroll
    for (int i = 0; i < FM; i++)
        #pragma unroll
        for (int j = 0; j < 2; j++)
            wmma::fill_fragment(cf[i][j], 0.0f);

    const int nk = K >> 5;
    gemm_issue<NT>(A, Bm, SA, SB, bm, bn, K, 0, 0, tid);

    for (int kt = 0; kt < nk; kt++) {
        const int st = kt & 1;
        if (kt + 1 < nk) {
            gemm_issue<NT>(A, Bm, SA, SB, bm, bn, K, kt + 1, st ^ 1, tid);
            asm volatile("cp.async.wait_group 1;");
        } else {
            asm volatile("cp.async.wait_group 0;");
        }
        __syncthreads();

        float* As = SA + st * 4608;
        float* Bs = SB + st * (NT * 36);
        #pragma unroll
        for (int kk = 0; kk < 4; kk++) {
            wmma::fragment<wmma::matrix_a, 16, 16, 8, wmma::precision::tf32, wmma::row_major> af[FM];
            #pragma unroll
            for (int i = 0; i < FM; i++)
                wmma::load_matrix_sync(af[i], &As[(wm * (FM * 16) + i * 16) * 36 + kk * 8], 36);
            wmma::fragment<wmma::matrix_b, 16, 16, 8, wmma::precision::tf32, wmma::col_major> bf[2];
            #pragma unroll
            for (int j = 0; j < 2; j++)
                wmma::load_matrix_sync(bf[j], &Bs[(wn * 32 + j * 16) * 36 + kk * 8], 36);
            #pragma unroll
            for (int i = 0; i < FM; i++)
                #pragma unroll
                for (int j = 0; j < 2; j++)
                    wmma::mma_sync(cf[i][j], af[i], bf[j], cf[i][j]);
        }
        __syncthreads();
    }

    #pragma unroll
    for (int i = 0; i < FM; i++)
        #pragma unroll
        for (int j = 0; j < 2; j++) {
            if (RND) {
                #pragma unroll
                for (int t = 0; t < cf[i][j].num_elements; t++)
                    cf[i][j].x[t] = rtf(cf[i][j].x[t]);
            }
            wmma::store_matrix_sync(
                &C[(long long)(bm * 128 + wm * (FM * 16) + i * 16) * N + bn * NT + wn * 32 + j * 16],
                cf[i][j], (unsigned)N, wmma::mem_row_major);
        }
}

template<int NT, bool RND>
__global__ __launch_bounds__(256, 2)
void gemm_nt(const float* __restrict__ A, const float* __restrict__ Bm,
             float* __restrict__ C, int N, int K)
{
    extern __shared__ float smg[];
    gemm_core<NT, RND>(A, Bm, C, blockIdx.y, blockIdx.x, N, K, smg);
}

// three GEMMs sharing A: B1(128-tiles), B2(128-tiles), B3(one 64-tile)
__global__ __launch_bounds__(256, 2)
void gemm_nt_tri(const float* __restrict__ A,
                 const float* __restrict__ B1, float* __restrict__ C1, int N1, int n1,
                 const float* __restrict__ B2, float* __restrict__ C2, int N2, int n2,
                 const float* __restrict__ B3, float* __restrict__ C3, int N3,
                 int K)
{
    extern __shared__ float smg[];
    int bx = blockIdx.x;
    if (bx < n1)           gemm_core<128, false>(A, B1, C1, blockIdx.y, bx, N1, K, smg);
    else if (bx < n1 + n2) gemm_core<128, false>(A, B2, C2, blockIdx.y, bx - n1, N2, K, smg);
    else                   gemm_core<64,  false>(A, B3, C3, blockIdx.y, 0, N3, K, smg);
}

// merged mid-pipeline launch: q_nope || q_pe || kv_up (rounded store)
__global__ __launch_bounds__(256, 2)
void gemm_mid(const float* __restrict__ qc,
              const float* __restrict__ w2, float* __restrict__ qn,
              const float* __restrict__ w3, float* __restrict__ qp,
              const float* __restrict__ kvc,
              const float* __restrict__ w5, float* __restrict__ kvu)
{
    extern __shared__ float smg[];
    int bx = blockIdx.x;
    if (bx < 16)      gemm_core<128, false>(qc,  w2, qn,  blockIdx.y, bx,      H_*NOPE_,          QR_,  smg);
    else if (bx < 24) gemm_core<128, false>(qc,  w3, qp,  blockIdx.y, bx - 16, H_*ROPE_,          QR_,  smg);
    else              gemm_core<128, true >(kvc, w5, kvu, blockIdx.y, bx - 24, H_*(NOPE_+VDIM_),  KVR_, smg);
}

// ---------------- single merged tf32 rounding pass ----------------
__device__ __forceinline__ void round_seg(const float* in, float* outp, long long n4,
                                          long long start, long long stride)
{
    for (long long i = start; i < n4; i += stride) {
        float4 v = ((const float4*)in)[i];
        ((float4*)outp)[i] = make_float4(rtf(v.x), rtf(v.y), rtf(v.z), rtf(v.w));
    }
}

__global__ void round_all_k(const float* x,  float* xr,
                            const float* a1, float* o1,
                            const float* a2, float* o2,
                            const float* a3, float* o3,
                            const float* a4, float* o4,
                            const float* a5, float* o5,
                            const float* a6, float* o6,
                            const float* a7, float* o7)
{
    long long start = (long long)blockIdx.x * 256 + threadIdx.x;
    long long stride = (long long)gridDim.x * 256;
    round_seg(x,  xr, (long long)MTOK * DIM_ / 4,               start, stride);
    round_seg(a1, o1, (long long)QR_ * DIM_ / 4,                start, stride);
    round_seg(a2, o2, (long long)H_ * NOPE_ * QR_ / 4,          start, stride);
    round_seg(a3, o3, (long long)H_ * ROPE_ * QR_ / 4,          start, stride);
    round_seg(a4, o4, (long long)KVR_ * DIM_ / 4,               start, stride);
    round_seg(a5, o5, (long long)H_ * (NOPE_+VDIM_) * KVR_ / 4, start, stride);
    round_seg(a6, o6, (long long)ROPE_ * DIM_ / 4,              start, stride);
    round_seg(a7, o7, (long long)DIM_ * H_ * VDIM_ / 4,         start, stride);
}

// =====================================================================
// Fused flash attention v6 (R11 exact): split-K PV with register P.
// =====================================================================
__global__ __launch_bounds__(256, 1)
void flash_attn(const float* __restrict__ qn, const float* __restrict__ qp,
                const float* __restrict__ kvu, const float* __restrict__ kr,
                float* __restrict__ outp)
{
    extern __shared__ float sm[];
    float* QS   = sm;          // [128][196]   (25088 floats)
    float* KS   = sm + 25088;  // [64][196]    (12544 floats)
    float* VS   = sm + 37632;  // [64][132]    (8448 floats)
    float* PMAX = sm + 46080;  // [2][128]
    float* LX   = sm + 46336;  // [128]
    float* OX   = sm + 25088;  // epilogue only: overlays KS+VS, [128][132]

    const int qt = (int)gridDim.x - 1 - (int)blockIdx.x;
    const int bh = blockIdx.y;
    const int b = bh >> 4, h = bh & 15;
    const int ib = qt * 128;
    const long long bs0 = (long long)b * S_;

    const int tid = threadIdx.x;
    const int w = tid >> 5, lane = tid & 31;
    const int wm = w & 3, wn = w >> 2;
    const int g = lane >> 2, t = lane & 3;
    const float scale = 0.07216878364870323f;

    const int ntiles = (ib + 128) / 64;

    // ---- preload K(0), V(0) as two groups ----
    {
        long long rowb = bs0;
        for (int i = tid; i < 64 * 48; i += 256) {
            int r = i / 48, c4 = i % 48;
            long long row = rowb + r;
            const float* src = (c4 < 32)
                ? &kvu[row * 4096 + h * 256 + c4 * 4]
                : &kr[row * 64 + (c4 - 32) * 4];
            cpasync16(&KS[r * 196 + c4 * 4], src);
        }
        asm volatile("cp.async.commit_group;");
        for (int i = tid; i < 64 * 32; i += 256) {
            int r = i / 32, c4 = i % 32;
            cpasync16(&VS[r * 132 + c4 * 4], &kvu[(rowb + r) * 4096 + h * 256 + 128 + c4 * 4]);
        }
        asm volatile("cp.async.commit_group;");
    }

    // ---- load Q tile (scaled + rounded) ----
    for (int i = tid; i < 128 * 48; i += 256) {
        int r = i / 48, c4 = (i % 48) * 4;
        long long row = bs0 + ib + r;
        float4 v;
        if (c4 < 128) v = *(const float4*)&qn[row * 2048 + h * 128 + c4];
        else          v = *(const float4*)&qp[row * 1024 + h * 64 + (c4 - 128)];
        float* d = &QS[r * 196 + c4];
        d[0] = rtf(v.x * scale); d[1] = rtf(v.y * scale);
        d[2] = rtf(v.z * scale); d[3] = rtf(v.w * scale);
    }

    float m[2][2] = {{-1e30f, -1e30f}, {-1e30f, -1e30f}};
    float l[2][2] = {{0.f, 0.f}, {0.f, 0.f}};
    float oacc[2][16][4] = {};

    const int srcl = (lane & 28) | (t >> 1);
    const int srch = srcl + 2;
    const bool todd = (t & 1);

    for (int kt = 0; kt < ntiles; kt++) {
        const int jb = kt * 64;

        asm volatile("cp.async.wait_group 1;");   // K(kt) ready
        __syncthreads();

        // ---- S = Q K^T ----
        float sacc[2][4][4] = {};
        #pragma unroll
        for (int k = 0; k < 24; k++) {
            unsigned a[2][4];
            #pragma unroll
            for (int mf = 0; mf < 2; mf++) {
                int r0 = wm * 32 + mf * 16 + g;
                a[mf][0] = __float_as_uint(QS[r0 * 196 + k * 8 + t]);
                a[mf][1] = __float_as_uint(QS[(r0 + 8) * 196 + k * 8 + t]);
                a[mf][2] = __float_as_uint(QS[r0 * 196 + k * 8 + t + 4]);
                a[mf][3] = __float_as_uint(QS[(r0 + 8) * 196 + k * 8 + t + 4]);
            }
            #pragma unroll
            for (int nf = 0; nf < 4; nf++) {
                unsigned bb[2];
                int n0 = wn * 32 + nf * 8 + g;
                bb[0] = __float_as_uint(KS[n0 * 196 + k * 8 + t]);
                bb[1] = __float_as_uint(KS[n0 * 196 + k * 8 + t + 4]);
                mma_tf32(sacc[0][nf], a[0], bb);
                mma_tf32(sacc[1][nf], a[1], bb);
            }
        }

        // ---- causal mask ----
        if (jb + 63 > ib) {
            #pragma unroll
            for (int mf = 0; mf < 2; mf++)
                #pragma unroll
                for (int nf = 0; nf < 4; nf++)
                    #pragma unroll
                    for (int e = 0; e < 4; e++) {
                        int row = ib + wm * 32 + mf * 16 + g + ((e >> 1) << 3);
                        int col = jb + wn * 32 + nf * 8 + 2 * t + (e & 1);
                        if (col > row) sacc[mf][nf][e] = -1e30f;
                    }
        }

        // ---- per-row max over own key half; publish ----
        float rmax[2][2];
        #pragma unroll
        for (int mf = 0; mf < 2; mf++)
            #pragma unroll
            for (int hf = 0; hf < 2; hf++) {
                float v = -1e30f;
                #pragma unroll
                for (int nf = 0; nf < 4; nf++)
                    v = fmaxf(v, fmaxf(sacc[mf][nf][2 * hf], sacc[mf][nf][2 * hf + 1]));
                v = fmaxf(v, __shfl_xor_sync(0xFFFFFFFF, v, 1));
                v = fmaxf(v, __shfl_xor_sync(0xFFFFFFFF, v, 2));
                rmax[mf][hf] = v;
            }
        if (t == 0) {
            #pragma unroll
            for (int mf = 0; mf < 2; mf++)
                #pragma unroll
                for (int hf = 0; hf < 2; hf++)
                    PMAX[wn * 128 + wm * 32 + mf * 16 + hf * 8 + g] = rmax[mf][hf];
        }
        __syncthreads();   // KS reads done + PMAX visible

        // ---- issue K(kt+1) ----
        if (kt + 1 < ntiles) {
            long long rowb = bs0 + jb + 64;
            for (int i = tid; i < 64 * 48; i += 256) {
                int r = i / 48, c4 = i % 48;
                long long row = rowb + r;
                const float* src = (c4 < 32)
                    ? &kvu[row * 4096 + h * 256 + c4 * 4]
                    : &kr[row * 64 + (c4 - 32) * 4];
                cpasync16(&KS[r * 196 + c4 * 4], src);
            }
            asm volatile("cp.async.commit_group;");
        }

        // ---- global m update ----
        float c[2][2];
        #pragma unroll
        for (int mf = 0; mf < 2; mf++)
            #pragma unroll
            for (int hf = 0; hf < 2; hf++) {
                float other = PMAX[(wn ^ 1) * 128 + wm * 32 + mf * 16 + hf * 8 + g];
                float mn = fmaxf(m[mf][hf], fmaxf(rmax[mf][hf], other));
                c[mf][hf] = __expf(m[mf][hf] - mn);
                m[mf][hf] = mn;
            }

        // ---- P = exp(S - m) in registers; shuffle into mma-A layout ----
        unsigned af[2][4][4];
        float rsum[2][2] = {};
        #pragma unroll
        for (int mf = 0; mf < 2; mf++) {
            #pragma unroll
            for (int nf = 0; nf < 4; nf++) {
                float p0 = rtf(__expf(sacc[mf][nf][0] - m[mf][0]));
                float p1 = rtf(__expf(sacc[mf][nf][1] - m[mf][0]));
                float p2 = rtf(__expf(sacc[mf][nf][2] - m[mf][1]));
                float p3 = rtf(__expf(sacc[mf][nf][3] - m[mf][1]));
                rsum[mf][0] += p0 + p1;
                rsum[mf][1] += p2 + p3;
                float y0, y1;
                y0 = __shfl_sync(0xFFFFFFFF, p0, srcl);
                y1 = __shfl_sync(0xFFFFFFFF, p1, srcl);
                af[mf][nf][0] = __float_as_uint(todd ? y1 : y0);
                y0 = __shfl_sync(0xFFFFFFFF, p2, srcl);
                y1 = __shfl_sync(0xFFFFFFFF, p3, srcl);
                af[mf][nf][1] = __float_as_uint(todd ? y1 : y0);
                y0 = __shfl_sync(0xFFFFFFFF, p0, srch);
                y1 = __shfl_sync(0xFFFFFFFF, p1, srch);
                af[mf][nf][2] = __float_as_uint(todd ? y1 : y0);
                y0 = __shfl_sync(0xFFFFFFFF, p2, srch);
                y1 = __shfl_sync(0xFFFFFFFF, p3, srch);
                af[mf][nf][3] = __float_as_uint(todd ? y1 : y0);
            }
        }
        #pragma unroll
        for (int mf = 0; mf < 2; mf++)
            #pragma unroll
            for (int hf = 0; hf < 2; hf++) {
                float v = rsum[mf][hf];
                v += __shfl_xor_sync(0xFFFFFFFF, v, 1);
                v += __shfl_xor_sync(0xFFFFFFFF, v, 2);
                l[mf][hf] = l[mf][hf] * c[mf][hf] + v;
            }

        // ---- rescale partial O ----
        #pragma unroll
        for (int mf = 0; mf < 2; mf++)
            #pragma unroll
            for (int nf = 0; nf < 16; nf++) {
                oacc[mf][nf][0] *= c[mf][0]; oacc[mf][nf][1] *= c[mf][0];
                oacc[mf][nf][2] *= c[mf][1]; oacc[mf][nf][3] *= c[mf][1];
            }

        // ---- V(kt) ready ----
        if (kt + 1 < ntiles) asm volatile("cp.async.wait_group 1;");
        else                 asm volatile("cp.async.wait_group 0;");
        __syncthreads();

        // ---- O_partial += P(own keys) V(own keys, :) ----
        #pragma unroll
        for (int kk = 0; kk < 4; kk++) {
            const int krow = wn * 32 + kk * 8;
            #pragma unroll
            for (int nf = 0; nf < 16; nf++) {
                unsigned bb[2];
                int n0 = nf * 8 + g;
                bb[0] = __float_as_uint(VS[(krow + t) * 132 + n0]);
                bb[1] = __float_as_uint(VS[(krow + t + 4) * 132 + n0]);
                mma_tf32(oacc[0][nf], af[0][kk], bb);
                mma_tf32(oacc[1][nf], af[1][kk], bb);
            }
        }
        __syncthreads();   // VS reads done

        // ---- issue V(kt+1) ----
        if (kt + 1 < ntiles) {
            long long rowb = bs0 + jb + 64;
            for (int i = tid; i < 64 * 32; i += 256) {
                int r = i / 32, c4 = i % 32;
                cpasync16(&VS[r * 132 + c4 * 4],
                          &kvu[(rowb + r) * 4096 + h * 256 + 128 + c4 * 4]);
            }
            asm volatile("cp.async.commit_group;");
        }
    }

    // ---- epilogue: reduce wn partials (O, l) and write out ----
    __syncthreads();
    if (wn == 1) {
        #pragma unroll
        for (int mf = 0; mf < 2; mf++) {
            int r0 = wm * 32 + mf * 16 + g;
            #pragma unroll
            for (int nf = 0; nf < 16; nf++) {
                int c2 = nf * 8 + 2 * t;
                *(float2*)&OX[r0 * 132 + c2]       = make_float2(oacc[mf][nf][0], oacc[mf][nf][1]);
                *(float2*)&OX[(r0 + 8) * 132 + c2] = make_float2(oacc[mf][nf][2], oacc[mf][nf][3]);
            }
            if (t == 0) { LX[r0] = l[mf][0]; LX[r0 + 8] = l[mf][1]; }
        }
    }
    __syncthreads();
    if (wn == 0) {
        #pragma unroll
        for (int mf = 0; mf < 2; mf++) {
            int r0 = wm * 32 + mf * 16 + g;
            float inv0 = 1.f / (l[mf][0] + LX[r0]);
            float inv1 = 1.f / (l[mf][1] + LX[r0 + 8]);
            long long o0 = (bs0 + ib + r0) * 2048 + h * 128;
            long long o1 = o0 + 8 * 2048;
            #pragma unroll
            for (int nf = 0; nf < 16; nf++) {
                int c2 = nf * 8 + 2 * t;
                float2 x0 = *(float2*)&OX[r0 * 132 + c2];
                float2 x1 = *(float2*)&OX[(r0 + 8) * 132 + c2];
                *(float2*)&outp[o0 + c2] =
                    make_float2(rtf((oacc[mf][nf][0] + x0.x) * inv0),
                                rtf((oacc[mf][nf][1] + x0.y) * inv0));
                *(float2*)&outp[o1 + c2] =
                    make_float2(rtf((oacc[mf][nf][2] + x1.x) * inv1),
                                rtf((oacc[mf][nf][3] + x1.y) * inv1));
            }
        }
    }
}

// ---------------- merged RMSNorm (qc, kvc) + k_rope RoPE ----------------
__global__ void rmsnorm_dual_k(float* __restrict__ xq, const float* __restrict__ wq,
                               float* __restrict__ xk, const float* __restrict__ wk,
                               float* __restrict__ kr)
{
    int bid = blockIdx.x;
    int tid = threadIdx.x;

    if (bid >= 2 * MTOK) {
        // RoPE on k_rope rows (32 threads useful)
        int row = bid - 2 * MTOK;
        if (tid < 32) {
            int s = row % S_;
            float* q = kr + (long long)row * ROPE_;
            float fr = (float)s * powf(10000.f, -(2.f * tid) / (float)ROPE_);
            float sn, c; sincosf(fr, &sn, &c);
            float x1 = q[2 * tid], x2 = q[2 * tid + 1];
            q[2 * tid]     = rtf(x1 * c - x2 * sn);
            q[2 * tid + 1] = rtf(x1 * sn + x2 * c);
        }
        return;
    }

    float* p;
    const float* wv;
    int N;
    if (bid < MTOK) { p = xq + (long long)bid * QR_;           wv = wq; N = QR_; }
    else            { p = xk + (long long)(bid - MTOK) * KVR_; wv = wk; N = KVR_; }
    float ss = 0.f;
    for (int i = tid; i < N; i += 256) { float v = p[i]; ss += v * v; }
    __shared__ float red[256];
    red[tid] = ss; __syncthreads();
    for (int s = 128; s > 0; s >>= 1) { if (tid < s) red[tid] += red[tid + s]; __syncthreads(); }
    float scale = rsqrtf(red[0] / N + 1e-6f);
    for (int i = tid; i < N; i += 256) p[i] = rtf(p[i] * scale * wv[i]);
}

// ---------------- RoPE on q_pe (write tf32-rounded) ----------------
__global__ void rope_q_k(float* __restrict__ qpe)
{
    int row = blockIdx.x;
    int s = row % S_;
    float* base = qpe + (long long)row * (H_ * ROPE_);
    for (int idx = threadIdx.x; idx < H_ * (ROPE_ / 2); idx += 256) {
        int h = idx >> 5, i = idx & 31;
        float fr = (float)s * powf(10000.f, -(2.f * i) / (float)ROPE_);
        float sn, c; sincosf(fr, &sn, &c);
        float* q = base + h * ROPE_;
        float x1 = q[2 * i], x2 = q[2 * i + 1];
        q[2 * i]     = rtf(x1 * c - x2 * sn);
        q[2 * i + 1] = rtf(x1 * sn + x2 * c);
    }
}

// ---------------- launch ----------------
extern "C" void kernel_launch(void* const* d_in, const int* in_sizes, int n_in,
                              void* d_out, int out_size)
{
    const float* x        = (const float*)d_in[0];
    const float* wq_down  = (const float*)d_in[1];
    const float* q_norm   = (const float*)d_in[2];
    const float* wq_up    = (const float*)d_in[3];
    const float* wq_rope  = (const float*)d_in[4];
    const float* wkv_down = (const float*)d_in[5];
    const float* kv_norm  = (const float*)d_in[6];
    const float* wkv_up   = (const float*)d_in[7];
    const float* wk_rope  = (const float*)d_in[8];
    const float* wo       = (const float*)d_in[9];
    float* out = (float*)d_out;

    float *qc, *qn, *qp, *kvc, *kvu, *kr, *attn;
    float *xr, *w1, *w2, *w3, *w4, *w5, *w6, *w7;
    cudaGetSymbolAddress((void**)&qc,   g_qc);
    cudaGetSymbolAddress((void**)&qn,   g_qnope);
    cudaGetSymbolAddress((void**)&qp,   g_qpe);
    cudaGetSymbolAddress((void**)&kvc,  g_kvc);
    cudaGetSymbolAddress((void**)&kvu,  g_kvup);
    cudaGetSymbolAddress((void**)&kr,   g_krope);
    cudaGetSymbolAddress((void**)&attn, g_attn);
    cudaGetSymbolAddress((void**)&xr,   g_xr);
    cudaGetSymbolAddress((void**)&w1,   g_w1);
    cudaGetSymbolAddress((void**)&w2,   g_w2);
    cudaGetSymbolAddress((void**)&w3,   g_w3);
    cudaGetSymbolAddress((void**)&w4,   g_w4);
    cudaGetSymbolAddress((void**)&w5,   g_w5);
    cudaGetSymbolAddress((void**)&w6,   g_w6);
    cudaGetSymbolAddress((void**)&w7,   g_w7);

    const int GS = 73728;      // gemm smem (2-stage, 128-tile)
    const int FS = 186368;     // flash smem

    cudaFuncSetAttribute((const void*)gemm_nt<128,false>, cudaFuncAttributeMaxDynamicSharedMemorySize, GS);
    cudaFuncSetAttribute((const void*)gemm_nt_tri,        cudaFuncAttributeMaxDynamicSharedMemorySize, GS);
    cudaFuncSetAttribute((const void*)gemm_mid,           cudaFuncAttributeMaxDynamicSharedMemorySize, GS);
    cudaFuncSetAttribute((const void*)flash_attn,         cudaFuncAttributeMaxDynamicSharedMemorySize, FS);

    dim3 blk(256);

    // ---- single merged rounding pass ----
    round_all_k<<<1184, 256>>>(x, xr, wq_down, w1, wq_up, w2, wq_rope, w3,
                               wkv_down, w4, wkv_up, w5, wk_rope, w6, wo, w7);

    // fused: q_c (8 tiles) || kv_c (4 tiles) || k_rope (1x64 tile), A = xr
    gemm_nt_tri<<<dim3(13, MTOK/128), blk, GS>>>(
        xr, w1, qc, QR_, QR_/128, w4, kvc, KVR_, KVR_/128, w6, kr, ROPE_, DIM_);

    // merged: rmsnorm(qc) + rmsnorm(kvc) + rope(kr), one launch
    rmsnorm_dual_k<<<3 * MTOK, 256>>>(qc, q_norm, kvc, kv_norm, kr);

    // merged mid GEMMs: q_nope || q_pe || kv_up
    gemm_mid<<<dim3(56, MTOK/128), blk, GS>>>(qc, w2, qn, w3, qp, kvc, w5, kvu);

    rope_q_k<<<MTOK, 256>>>(qp);

    // fused attention -> attn (tf32-rounded)
    flash_attn<<<dim3(S_/128, BH_), 256, FS>>>(qn, qp, kvu, kr, attn);
    // out = attn @ wo^T
    gemm_nt<128,false><<<dim3(DIM_/128, MTOK/128), blk, GS>>>(attn, w7, out, DIM_, DIM_);
}

// round 16
// speedup vs baseline: 2.4126x; 2.2720x over previous
#include <cuda_runtime.h>
#include <cuda_fp16.h>
#include <math.h>
#include <cstdint>
#include <mma.h>
using namespace nvcuda;

// ---------------- problem constants ----------------
#define B_    2
#define S_    2048
#define DIM_  2048
#define H_    16
#define NOPE_ 128
#define ROPE_ 64
#define VDIM_ 128
#define QR_   1024
#define KVR_  512
#define MTOK  (B_*S_)          // 4096
#define QKD   (NOPE_+ROPE_)    // 192
#define BH_   (B_*H_)          // 32

// ---------------- scratch ----------------
__device__ float  g_qc   [(long long)MTOK*QR_];
__device__ float  g_qnope[(long long)MTOK*H_*NOPE_];
__device__ float  g_qpe  [(long long)MTOK*H_*ROPE_];
__device__ float  g_kvc  [(long long)MTOK*KVR_];
__device__ float  g_kvup [(long long)MTOK*H_*(NOPE_+VDIM_)];
__device__ float  g_krope[(long long)MTOK*ROPE_];
// fp16 operand copies / intermediates
__device__ __half g_xrh [(long long)MTOK*DIM_];
__device__ __half g_w1h [(long long)QR_*DIM_];
__device__ __half g_w2h [(long long)H_*NOPE_*QR_];
__device__ __half g_w3h [(long long)H_*ROPE_*QR_];
__device__ __half g_w4h [(long long)KVR_*DIM_];
__device__ __half g_w5h [(long long)H_*(NOPE_+VDIM_)*KVR_];
__device__ __half g_w6h [(long long)ROPE_*DIM_];
__device__ __half g_w7h [(long long)DIM_*H_*VDIM_];
__device__ __half g_qch [(long long)MTOK*QR_];
__device__ __half g_kvch[(long long)MTOK*KVR_];
__device__ __half g_attnh[(long long)MTOK*H_*VDIM_];

// ---------------- helpers ----------------
__device__ __forceinline__ unsigned f2tf(float f) {
    unsigned r; asm("cvt.rna.tf32.f32 %0, %1;" : "=r"(r) : "f"(f)); return r;
}
__device__ __forceinline__ float rtf(float x) { return __uint_as_float(f2tf(x)); }

__device__ __forceinline__ void mma_tf32(float c[4], const unsigned a[4], const unsigned b[2]) {
    asm volatile(
        "mma.sync.aligned.m16n8k8.row.col.f32.tf32.tf32.f32 "
        "{%0,%1,%2,%3},{%4,%5,%6,%7},{%8,%9},{%0,%1,%2,%3};"
        : "+f"(c[0]), "+f"(c[1]), "+f"(c[2]), "+f"(c[3])
        : "r"(a[0]), "r"(a[1]), "r"(a[2]), "r"(a[3]), "r"(b[0]), "r"(b[1]));
}

__device__ __forceinline__ void cpasync16(void* s, const void* g) {
    unsigned saddr = (unsigned)__cvta_generic_to_shared(s);
    asm volatile("cp.async.ca.shared.global [%0], [%1], 16;" :: "r"(saddr), "l"(g));
}

// =====================================================================
// NT FP16 GEMM (fp32 accumulate), cp.async 2-stage, tile 128 x NT x 64,
// 8 warps. B stored [N,K]. RND: tf32-round C at store (for flash input).
// smem row stride 72 halves (144B, conflict-free, 16B aligned).
// =====================================================================
template<int NT>
__device__ __forceinline__ void gemm_issue(const __half* A, const __half* B,
                                           __half* SA, __half* SB,
                                           int bm, int bn, int K, int kt, int st, int tid)
{
    const int k0 = kt << 6;
    #pragma unroll
    for (int l = 0; l < 4; l++) {
        int idx = tid + (l << 8);
        int r = idx >> 3, c8 = (idx & 7) << 3;
        cpasync16(&SA[st * 9216 + r * 72 + c8], &A[(long long)(bm * 128 + r) * K + k0 + c8]);
    }
    #pragma unroll
    for (int l = 0; l < NT / 32; l++) {
        int idx = tid + (l << 8);
        int r = idx >> 3, c8 = (idx & 7) << 3;
        cpasync16(&SB[st * (NT * 72) + r * 72 + c8], &B[(long long)(bn * NT + r) * K + k0 + c8]);
    }
    asm volatile("cp.async.commit_group;");
}

template<int NT, bool RND>
__device__ __forceinline__ void gemm_core(const __half* A, const __half* Bm, float* C,
                                          int bm, int bn, int N, int K, __half* smg)
{
    __half* SA = smg;                   // [2][128*72]
    __half* SB = smg + 2 * 9216;        // [2][NT*72]

    constexpr int WN = NT / 32;
    constexpr int WMC = 8 / WN;
    constexpr int FM = (128 / WMC) / 16;

    const int tid = threadIdx.x;
    const int w = tid >> 5;
    const int wm = w / WN, wn = w % WN;

    wmma::fragment<wmma::accumulator, 16, 16, 16, float> cf[FM][2];
    #pragma unroll
    for (int i = 0; i < FM; i++)
        #pragma unroll
        for (int j = 0; j < 2; j++)
            wmma::fill_fragment(cf[i][j], 0.0f);

    const int nk = K >> 6;
    gemm_issue<NT>(A, Bm, SA, SB, bm, bn, K, 0, 0, tid);

    for (int kt = 0; kt < nk; kt++) {
        const int st = kt & 1;
        if (kt + 1 < nk) {
            gemm_issue<NT>(A, Bm, SA, SB, bm, bn, K, kt + 1, st ^ 1, tid);
            asm volatile("cp.async.wait_group 1;");
        } else {
            asm volatile("cp.async.wait_group 0;");
        }
        __syncthreads();

        __half* As = SA + st * 9216;
        __half* Bs = SB + st * (NT * 72);
        #pragma unroll
        for (int kk = 0; kk < 4; kk++) {
            wmma::fragment<wmma::matrix_a, 16, 16, 16, __half, wmma::row_major> af[FM];
            #pragma unroll
            for (int i = 0; i < FM; i++)
                wmma::load_matrix_sync(af[i], &As[(wm * (FM * 16) + i * 16) * 72 + kk * 16], 72);
            wmma::fragment<wmma::matrix_b, 16, 16, 16, __half, wmma::col_major> bf[2];
            #pragma unroll
            for (int j = 0; j < 2; j++)
                wmma::load_matrix_sync(bf[j], &Bs[(wn * 32 + j * 16) * 72 + kk * 16], 72);
            #pragma unroll
            for (int i = 0; i < FM; i++)
                #pragma unroll
                for (int j = 0; j < 2; j++)
                    wmma::mma_sync(cf[i][j], af[i], bf[j], cf[i][j]);
        }
        __syncthreads();
    }

    #pragma unroll
    for (int i = 0; i < FM; i++)
        #pragma unroll
        for (int j = 0; j < 2; j++) {
            if (RND) {
                #pragma unroll
                for (int t = 0; t < cf[i][j].num_elements; t++)
                    cf[i][j].x[t] = rtf(cf[i][j].x[t]);
            }
            wmma::store_matrix_sync(
                &C[(long long)(bm * 128 + wm * (FM * 16) + i * 16) * N + bn * NT + wn * 32 + j * 16],
                cf[i][j], (unsigned)N, wmma::mem_row_major);
        }
}

template<int NT, bool RND>
__global__ __launch_bounds__(256, 2)
void gemm_nt(const __half* __restrict__ A, const __half* __restrict__ Bm,
             float* __restrict__ C, int N, int K)
{
    extern __shared__ __half smg[];
    gemm_core<NT, RND>(A, Bm, C, blockIdx.y, blockIdx.x, N, K, smg);
}

// three GEMMs sharing A: B1(128-tiles), B2(128-tiles), B3(one 64-tile)
__global__ __launch_bounds__(256, 2)
void gemm_nt_tri(const __half* __restrict__ A,
                 const __half* __restrict__ B1, float* __restrict__ C1, int N1, int n1,
                 const __half* __restrict__ B2, float* __restrict__ C2, int N2, int n2,
                 const __half* __restrict__ B3, float* __restrict__ C3, int N3,
                 int K)
{
    extern __shared__ __half smg[];
    int bx = blockIdx.x;
    if (bx < n1)           gemm_core<128, false>(A, B1, C1, blockIdx.y, bx, N1, K, smg);
    else if (bx < n1 + n2) gemm_core<128, false>(A, B2, C2, blockIdx.y, bx - n1, N2, K, smg);
    else                   gemm_core<64,  false>(A, B3, C3, blockIdx.y, 0, N3, K, smg);
}

// merged mid-pipeline launch: q_nope || q_pe || kv_up (rounded store)
__global__ __launch_bounds__(256, 2)
void gemm_mid(const __half* __restrict__ qc,
              const __half* __restrict__ w2, float* __restrict__ qn,
              const __half* __restrict__ w3, float* __restrict__ qp,
              const __half* __restrict__ kvc,
              const __half* __restrict__ w5, float* __restrict__ kvu)
{
    extern __shared__ __half smg[];
    int bx = blockIdx.x;
    if (bx < 16)      gemm_core<128, false>(qc,  w2, qn,  blockIdx.y, bx,      H_*NOPE_,          QR_,  smg);
    else if (bx < 24) gemm_core<128, false>(qc,  w3, qp,  blockIdx.y, bx - 16, H_*ROPE_,          QR_,  smg);
    else              gemm_core<128, true >(kvc, w5, kvu, blockIdx.y, bx - 24, H_*(NOPE_+VDIM_),  KVR_, smg);
}

// ---------------- single merged fp16 conversion pass ----------------
__device__ __forceinline__ void half_seg(const float* in, __half* outp, long long n4,
                                         long long start, long long stride)
{
    for (long long i = start; i < n4; i += stride) {
        float4 v = ((const float4*)in)[i];
        ((__half2*)outp)[i * 2]     = __floats2half2_rn(v.x, v.y);
        ((__half2*)outp)[i * 2 + 1] = __floats2half2_rn(v.z, v.w);
    }
}

__global__ void half_all_k(const float* x,  __half* xr,
                           const float* a1, __half* o1,
                           const float* a2, __half* o2,
                           const float* a3, __half* o3,
                           const float* a4, __half* o4,
                           const float* a5, __half* o5,
                           const float* a6, __half* o6,
                           const float* a7, __half* o7)
{
    long long start = (long long)blockIdx.x * 256 + threadIdx.x;
    long long stride = (long long)gridDim.x * 256;
    half_seg(x,  xr, (long long)MTOK * DIM_ / 4,               start, stride);
    half_seg(a1, o1, (long long)QR_ * DIM_ / 4,                start, stride);
    half_seg(a2, o2, (long long)H_ * NOPE_ * QR_ / 4,          start, stride);
    half_seg(a3, o3, (long long)H_ * ROPE_ * QR_ / 4,          start, stride);
    half_seg(a4, o4, (long long)KVR_ * DIM_ / 4,               start, stride);
    half_seg(a5, o5, (long long)H_ * (NOPE_+VDIM_) * KVR_ / 4, start, stride);
    half_seg(a6, o6, (long long)ROPE_ * DIM_ / 4,              start, stride);
    half_seg(a7, o7, (long long)DIM_ * H_ * VDIM_ / 4,         start, stride);
}

// =====================================================================
// Fused flash attention v6 (R11): split-K PV with register P; tf32 mma.
// Epilogue writes __half attn for the fp16 output GEMM.
// =====================================================================
__global__ __launch_bounds__(256, 1)
void flash_attn(const float* __restrict__ qn, const float* __restrict__ qp,
                const float* __restrict__ kvu, const float* __restrict__ kr,
                __half* __restrict__ outp)
{
    extern __shared__ float sm[];
    float* QS   = sm;          // [128][196]
    float* KS   = sm + 25088;  // [64][196]
    float* VS   = sm + 37632;  // [64][132]
    float* PMAX = sm + 46080;  // [2][128]
    float* LX   = sm + 46336;  // [128]
    float* OX   = sm + 25088;  // epilogue only: overlays KS+VS

    const int qt = (int)gridDim.x - 1 - (int)blockIdx.x;
    const int bh = blockIdx.y;
    const int b = bh >> 4, h = bh & 15;
    const int ib = qt * 128;
    const long long bs0 = (long long)b * S_;

    const int tid = threadIdx.x;
    const int w = tid >> 5, lane = tid & 31;
    const int wm = w & 3, wn = w >> 2;
    const int g = lane >> 2, t = lane & 3;
    const float scale = 0.07216878364870323f;

    const int ntiles = (ib + 128) / 64;

    // ---- preload K(0), V(0) ----
    {
        long long rowb = bs0;
        for (int i = tid; i < 64 * 48; i += 256) {
            int r = i / 48, c4 = i % 48;
            long long row = rowb + r;
            const float* src = (c4 < 32)
                ? &kvu[row * 4096 + h * 256 + c4 * 4]
                : &kr[row * 64 + (c4 - 32) * 4];
            cpasync16(&KS[r * 196 + c4 * 4], src);
        }
        asm volatile("cp.async.commit_group;");
        for (int i = tid; i < 64 * 32; i += 256) {
            int r = i / 32, c4 = i % 32;
            cpasync16(&VS[r * 132 + c4 * 4], &kvu[(rowb + r) * 4096 + h * 256 + 128 + c4 * 4]);
        }
        asm volatile("cp.async.commit_group;");
    }

    // ---- load Q tile (scaled + rounded) ----
    for (int i = tid; i < 128 * 48; i += 256) {
        int r = i / 48, c4 = (i % 48) * 4;
        long long row = bs0 + ib + r;
        float4 v;
        if (c4 < 128) v = *(const float4*)&qn[row * 2048 + h * 128 + c4];
        else          v = *(const float4*)&qp[row * 1024 + h * 64 + (c4 - 128)];
        float* d = &QS[r * 196 + c4];
        d[0] = rtf(v.x * scale); d[1] = rtf(v.y * scale);
        d[2] = rtf(v.z * scale); d[3] = rtf(v.w * scale);
    }

    float m[2][2] = {{-1e30f, -1e30f}, {-1e30f, -1e30f}};
    float l[2][2] = {{0.f, 0.f}, {0.f, 0.f}};
    float oacc[2][16][4] = {};

    const int srcl = (lane & 28) | (t >> 1);
    const int srch = srcl + 2;
    const bool todd = (t & 1);

    for (int kt = 0; kt < ntiles; kt++) {
        const int jb = kt * 64;

        asm volatile("cp.async.wait_group 1;");
        __syncthreads();

        float sacc[2][4][4] = {};
        #pragma unroll
        for (int k = 0; k < 24; k++) {
            unsigned a[2][4];
            #pragma unroll
            for (int mf = 0; mf < 2; mf++) {
                int r0 = wm * 32 + mf * 16 + g;
                a[mf][0] = __float_as_uint(QS[r0 * 196 + k * 8 + t]);
                a[mf][1] = __float_as_uint(QS[(r0 + 8) * 196 + k * 8 + t]);
                a[mf][2] = __float_as_uint(QS[r0 * 196 + k * 8 + t + 4]);
                a[mf][3] = __float_as_uint(QS[(r0 + 8) * 196 + k * 8 + t + 4]);
            }
            #pragma unroll
            for (int nf = 0; nf < 4; nf++) {
                unsigned bb[2];
                int n0 = wn * 32 + nf * 8 + g;
                bb[0] = __float_as_uint(KS[n0 * 196 + k * 8 + t]);
                bb[1] = __float_as_uint(KS[n0 * 196 + k * 8 + t + 4]);
                mma_tf32(sacc[0][nf], a[0], bb);
                mma_tf32(sacc[1][nf], a[1], bb);
            }
        }

        if (jb + 63 > ib) {
            #pragma unroll
            for (int mf = 0; mf < 2; mf++)
                #pragma unroll
                for (int nf = 0; nf < 4; nf++)
                    #pragma unroll
                    for (int e = 0; e < 4; e++) {
                        int row = ib + wm * 32 + mf * 16 + g + ((e >> 1) << 3);
                        int col = jb + wn * 32 + nf * 8 + 2 * t + (e & 1);
                        if (col > row) sacc[mf][nf][e] = -1e30f;
                    }
        }

        float rmax[2][2];
        #pragma unroll
        for (int mf = 0; mf < 2; mf++)
            #pragma unroll
            for (int hf = 0; hf < 2; hf++) {
                float v = -1e30f;
                #pragma unroll
                for (int nf = 0; nf < 4; nf++)
                    v = fmaxf(v, fmaxf(sacc[mf][nf][2 * hf], sacc[mf][nf][2 * hf + 1]));
                v = fmaxf(v, __shfl_xor_sync(0xFFFFFFFF, v, 1));
                v = fmaxf(v, __shfl_xor_sync(0xFFFFFFFF, v, 2));
                rmax[mf][hf] = v;
            }
        if (t == 0) {
            #pragma unroll
            for (int mf = 0; mf < 2; mf++)
                #pragma unroll
                for (int hf = 0; hf < 2; hf++)
                    PMAX[wn * 128 + wm * 32 + mf * 16 + hf * 8 + g] = rmax[mf][hf];
        }
        __syncthreads();

        if (kt + 1 < ntiles) {
            long long rowb = bs0 + jb + 64;
            for (int i = tid; i < 64 * 48; i += 256) {
                int r = i / 48, c4 = i % 48;
                long long row = rowb + r;
                const float* src = (c4 < 32)
                    ? &kvu[row * 4096 + h * 256 + c4 * 4]
                    : &kr[row * 64 + (c4 - 32) * 4];
                cpasync16(&KS[r * 196 + c4 * 4], src);
            }
            asm volatile("cp.async.commit_group;");
        }

        float c[2][2];
        #pragma unroll
        for (int mf = 0; mf < 2; mf++)
            #pragma unroll
            for (int hf = 0; hf < 2; hf++) {
                float other = PMAX[(wn ^ 1) * 128 + wm * 32 + mf * 16 + hf * 8 + g];
                float mn = fmaxf(m[mf][hf], fmaxf(rmax[mf][hf], other));
                c[mf][hf] = __expf(m[mf][hf] - mn);
                m[mf][hf] = mn;
            }

        unsigned af[2][4][4];
        float rsum[2][2] = {};
        #pragma unroll
        for (int mf = 0; mf < 2; mf++) {
            #pragma unroll
            for (int nf = 0; nf < 4; nf++) {
                float p0 = rtf(__expf(sacc[mf][nf][0] - m[mf][0]));
                float p1 = rtf(__expf(sacc[mf][nf][1] - m[mf][0]));
                float p2 = rtf(__expf(sacc[mf][nf][2] - m[mf][1]));
                float p3 = rtf(__expf(sacc[mf][nf][3] - m[mf][1]));
                rsum[mf][0] += p0 + p1;
                rsum[mf][1] += p2 + p3;
                float y0, y1;
                y0 = __shfl_sync(0xFFFFFFFF, p0, srcl);
                y1 = __shfl_sync(0xFFFFFFFF, p1, srcl);
                af[mf][nf][0] = __float_as_uint(todd ? y1 : y0);
                y0 = __shfl_sync(0xFFFFFFFF, p2, srcl);
                y1 = __shfl_sync(0xFFFFFFFF, p3, srcl);
                af[mf][nf][1] = __float_as_uint(todd ? y1 : y0);
                y0 = __shfl_sync(0xFFFFFFFF, p0, srch);
                y1 = __shfl_sync(0xFFFFFFFF, p1, srch);
                af[mf][nf][2] = __float_as_uint(todd ? y1 : y0);
                y0 = __shfl_sync(0xFFFFFFFF, p2, srch);
                y1 = __shfl_sync(0xFFFFFFFF, p3, srch);
                af[mf][nf][3] = __float_as_uint(todd ? y1 : y0);
            }
        }
        #pragma unroll
        for (int mf = 0; mf < 2; mf++)
            #pragma unroll
            for (int hf = 0; hf < 2; hf++) {
                float v = rsum[mf][hf];
                v += __shfl_xor_sync(0xFFFFFFFF, v, 1);
                v += __shfl_xor_sync(0xFFFFFFFF, v, 2);
                l[mf][hf] = l[mf][hf] * c[mf][hf] + v;
            }

        #pragma unroll
        for (int mf = 0; mf < 2; mf++)
            #pragma unroll
            for (int nf = 0; nf < 16; nf++) {
                oacc[mf][nf][0] *= c[mf][0]; oacc[mf][nf][1] *= c[mf][0];
                oacc[mf][nf][2] *= c[mf][1]; oacc[mf][nf][3] *= c[mf][1];
            }

        if (kt + 1 < ntiles) asm volatile("cp.async.wait_group 1;");
        else                 asm volatile("cp.async.wait_group 0;");
        __syncthreads();

        #pragma unroll
        for (int kk = 0; kk < 4; kk++) {
            const int krow = wn * 32 + kk * 8;
            #pragma unroll
            for (int nf = 0; nf < 16; nf++) {
                unsigned bb[2];
                int n0 = nf * 8 + g;
                bb[0] = __float_as_uint(VS[(krow + t) * 132 + n0]);
                bb[1] = __float_as_uint(VS[(krow + t + 4) * 132 + n0]);
                mma_tf32(oacc[0][nf], af[0][kk], bb);
                mma_tf32(oacc[1][nf], af[1][kk], bb);
            }
        }
        __syncthreads();

        if (kt + 1 < ntiles) {
            long long rowb = bs0 + jb + 64;
            for (int i = tid; i < 64 * 32; i += 256) {
                int r = i / 32, c4 = i % 32;
                cpasync16(&VS[r * 132 + c4 * 4],
                          &kvu[(rowb + r) * 4096 + h * 256 + 128 + c4 * 4]);
            }
            asm volatile("cp.async.commit_group;");
        }
    }

    // ---- epilogue: reduce wn partials and write __half attn ----
    __syncthreads();
    if (wn == 1) {
        #pragma unroll
        for (int mf = 0; mf < 2; mf++) {
            int r0 = wm * 32 + mf * 16 + g;
            #pragma unroll
            for (int nf = 0; nf < 16; nf++) {
                int c2 = nf * 8 + 2 * t;
                *(float2*)&OX[r0 * 132 + c2]       = make_float2(oacc[mf][nf][0], oacc[mf][nf][1]);
                *(float2*)&OX[(r0 + 8) * 132 + c2] = make_float2(oacc[mf][nf][2], oacc[mf][nf][3]);
            }
            if (t == 0) { LX[r0] = l[mf][0]; LX[r0 + 8] = l[mf][1]; }
        }
    }
    __syncthreads();
    if (wn == 0) {
        #pragma unroll
        for (int mf = 0; mf < 2; mf++) {
            int r0 = wm * 32 + mf * 16 + g;
            float inv0 = 1.f / (l[mf][0] + LX[r0]);
            float inv1 = 1.f / (l[mf][1] + LX[r0 + 8]);
            long long o0 = (bs0 + ib + r0) * 2048 + h * 128;
            long long o1 = o0 + 8 * 2048;
            #pragma unroll
            for (int nf = 0; nf < 16; nf++) {
                int c2 = nf * 8 + 2 * t;
                float2 x0 = *(float2*)&OX[r0 * 132 + c2];
                float2 x1 = *(float2*)&OX[(r0 + 8) * 132 + c2];
                *(__half2*)&outp[o0 + c2] =
                    __floats2half2_rn((oacc[mf][nf][0] + x0.x) * inv0,
                                      (oacc[mf][nf][1] + x0.y) * inv0);
                *(__half2*)&outp[o1 + c2] =
                    __floats2half2_rn((oacc[mf][nf][2] + x1.x) * inv1,
                                      (oacc[mf][nf][3] + x1.y) * inv1);
            }
        }
    }
}

// ---------------- merged RMSNorm (fp32 in -> fp16 out) + k_rope RoPE ----------------
__global__ void rmsnorm_dual_k(const float* __restrict__ xq, const float* __restrict__ wq,
                               __half* __restrict__ oq,
                               const float* __restrict__ xk, const float* __restrict__ wk,
                               __half* __restrict__ ok,
                               float* __restrict__ kr)
{
    int bid = blockIdx.x;
    int tid = threadIdx.x;

    if (bid >= 2 * MTOK) {
        int row = bid - 2 * MTOK;
        if (tid < 32) {
            int s = row % S_;
            float* q = kr + (long long)row * ROPE_;
            float fr = (float)s * powf(10000.f, -(2.f * tid) / (float)ROPE_);
            float sn, c; sincosf(fr, &sn, &c);
            float x1 = q[2 * tid], x2 = q[2 * tid + 1];
            q[2 * tid]     = rtf(x1 * c - x2 * sn);
            q[2 * tid + 1] = rtf(x1 * sn + x2 * c);
        }
        return;
    }

    const float* p;
    const float* wv;
    __half* o;
    int N;
    if (bid < MTOK) { p = xq + (long long)bid * QR_;           wv = wq; o = oq + (long long)bid * QR_;          N = QR_; }
    else            { p = xk + (long long)(bid - MTOK) * KVR_; wv = wk; o = ok + (long long)(bid - MTOK) * KVR_; N = KVR_; }
    float ss = 0.f;
    for (int i = tid; i < N; i += 256) { float v = p[i]; ss += v * v; }
    __shared__ float red[256];
    red[tid] = ss; __syncthreads();
    for (int s = 128; s > 0; s >>= 1) { if (tid < s) red[tid] += red[tid + s]; __syncthreads(); }
    float scale = rsqrtf(red[0] / N + 1e-6f);
    for (int i = tid; i < N; i += 256) o[i] = __float2half_rn(p[i] * scale * wv[i]);
}

// ---------------- RoPE on q_pe (write tf32-rounded) ----------------
__global__ void rope_q_k(float* __restrict__ qpe)
{
    int row = blockIdx.x;
    int s = row % S_;
    float* base = qpe + (long long)row * (H_ * ROPE_);
    for (int idx = threadIdx.x; idx < H_ * (ROPE_ / 2); idx += 256) {
        int h = idx >> 5, i = idx & 31;
        float fr = (float)s * powf(10000.f, -(2.f * i) / (float)ROPE_);
        float sn, c; sincosf(fr, &sn, &c);
        float* q = base + h * ROPE_;
        float x1 = q[2 * i], x2 = q[2 * i + 1];
        q[2 * i]     = rtf(x1 * c - x2 * sn);
        q[2 * i + 1] = rtf(x1 * sn + x2 * c);
    }
}

// ---------------- launch ----------------
extern "C" void kernel_launch(void* const* d_in, const int* in_sizes, int n_in,
                              void* d_out, int out_size)
{
    const float* x        = (const float*)d_in[0];
    const float* wq_down  = (const float*)d_in[1];
    const float* q_norm   = (const float*)d_in[2];
    const float* wq_up    = (const float*)d_in[3];
    const float* wq_rope  = (const float*)d_in[4];
    const float* wkv_down = (const float*)d_in[5];
    const float* kv_norm  = (const float*)d_in[6];
    const float* wkv_up   = (const float*)d_in[7];
    const float* wk_rope  = (const float*)d_in[8];
    const float* wo       = (const float*)d_in[9];
    float* out = (float*)d_out;

    float *qc, *qn, *qp, *kvc, *kvu, *kr;
    __half *xrh, *w1h, *w2h, *w3h, *w4h, *w5h, *w6h, *w7h, *qch, *kvch, *attnh;
    cudaGetSymbolAddress((void**)&qc,    g_qc);
    cudaGetSymbolAddress((void**)&qn,    g_qnope);
    cudaGetSymbolAddress((void**)&qp,    g_qpe);
    cudaGetSymbolAddress((void**)&kvc,   g_kvc);
    cudaGetSymbolAddress((void**)&kvu,   g_kvup);
    cudaGetSymbolAddress((void**)&kr,    g_krope);
    cudaGetSymbolAddress((void**)&xrh,   g_xrh);
    cudaGetSymbolAddress((void**)&w1h,   g_w1h);
    cudaGetSymbolAddress((void**)&w2h,   g_w2h);
    cudaGetSymbolAddress((void**)&w3h,   g_w3h);
    cudaGetSymbolAddress((void**)&w4h,   g_w4h);
    cudaGetSymbolAddress((void**)&w5h,   g_w5h);
    cudaGetSymbolAddress((void**)&w6h,   g_w6h);
    cudaGetSymbolAddress((void**)&w7h,   g_w7h);
    cudaGetSymbolAddress((void**)&qch,   g_qch);
    cudaGetSymbolAddress((void**)&kvch,  g_kvch);
    cudaGetSymbolAddress((void**)&attnh, g_attnh);

    const int GS = 73728;      // gemm smem: 2 stages x (128+128) x 72 halves
    const int FS = 186368;     // flash smem

    cudaFuncSetAttribute((const void*)gemm_nt<128,false>, cudaFuncAttributeMaxDynamicSharedMemorySize, GS);
    cudaFuncSetAttribute((const void*)gemm_nt_tri,        cudaFuncAttributeMaxDynamicSharedMemorySize, GS);
    cudaFuncSetAttribute((const void*)gemm_mid,           cudaFuncAttributeMaxDynamicSharedMemorySize, GS);
    cudaFuncSetAttribute((const void*)flash_attn,         cudaFuncAttributeMaxDynamicSharedMemorySize, FS);

    dim3 blk(256);

    // ---- single merged fp16 conversion pass ----
    half_all_k<<<1184, 256>>>(x, xrh, wq_down, w1h, wq_up, w2h, wq_rope, w3h,
                              wkv_down, w4h, wkv_up, w5h, wk_rope, w6h, wo, w7h);

    // fused: q_c (8 tiles) || kv_c (4 tiles) || k_rope (1x64 tile), A = xrh
    gemm_nt_tri<<<dim3(13, MTOK/128), blk, GS>>>(
        xrh, w1h, qc, QR_, QR_/128, w4h, kvc, KVR_, KVR_/128, w6h, kr, ROPE_, DIM_);

    // merged: rmsnorm(qc)->qch + rmsnorm(kvc)->kvch + rope(kr), one launch
    rmsnorm_dual_k<<<3 * MTOK, 256>>>(qc, q_norm, qch, kvc, kv_norm, kvch, kr);

    // merged mid GEMMs: q_nope || q_pe || kv_up
    gemm_mid<<<dim3(56, MTOK/128), blk, GS>>>(qch, w2h, qn, w3h, qp, kvch, w5h, kvu);

    rope_q_k<<<MTOK, 256>>>(qp);

    // fused attention -> attnh (fp16)
    flash_attn<<<dim3(S_/128, BH_), 256, FS>>>(qn, qp, kvu, kr, attnh);
    // out = attn @ wo^T (fp16 operands, fp32 out)
    gemm_nt<128,false><<<dim3(DIM_/128, MTOK/128), blk, GS>>>(attnh, w7h, out, DIM_, DIM_);
}